// round 8
// baseline (speedup 1.0000x reference)
#include <cuda_runtime.h>
#include <cuda_bf16.h>
#include <cstdint>

// Fixed problem shape: N = M = 8192, D = 128, fp32 in/out.
#define DMAX 128
#define NMAX 8192

// Scratch (device globals — no allocation allowed in kernel_launch)
__device__ __align__(16) __nv_bfloat16 g_Abf[NMAX * DMAX];
__device__ __align__(16) __nv_bfloat16 g_Bbf[NMAX * DMAX];
__device__ float g_a2[NMAX];
__device__ float g_b2[NMAX];

// ---------------------------------------------------------------------------
// Fused prep: one WARP per row across both matrices.
// ---------------------------------------------------------------------------
__global__ void prep_fused(const float* __restrict__ A, const float* __restrict__ B,
                           int N, int M) {
    const int warp = (blockIdx.x * blockDim.x + threadIdx.x) >> 5;
    const int lane = threadIdx.x & 31;
    if (warp >= N + M) return;

    const bool isA = warp < N;
    const int row = isA ? warp : warp - N;
    const float* src = (isA ? A : B) + (size_t)row * DMAX;

    float4 v = reinterpret_cast<const float4*>(src)[lane];

    __nv_bfloat162 lo = __floats2bfloat162_rn(v.x, v.y);
    __nv_bfloat162 hi = __floats2bfloat162_rn(v.z, v.w);
    uint2 packed = make_uint2(*reinterpret_cast<unsigned*>(&lo),
                              *reinterpret_cast<unsigned*>(&hi));
    __nv_bfloat16* dst = (isA ? g_Abf : g_Bbf) + (size_t)row * DMAX;
    reinterpret_cast<uint2*>(dst)[lane] = packed;

    float s = fmaf(v.x, v.x, fmaf(v.y, v.y, fmaf(v.z, v.z, v.w * v.w)));
    #pragma unroll
    for (int off = 16; off > 0; off >>= 1)
        s += __shfl_xor_sync(0xFFFFFFFFu, s, off);
    if (lane == 0) {
        if (isA) g_a2[row] = s;
        else     g_b2[row] = s;
    }
}

// ---------------------------------------------------------------------------
// Persistent pipelined GEMM + fused distance epilogue (mma.sync path —
// tcgen05 PTX is rejected by the harness's compute_103 PTX stage).
// CTA tile 128x128; K=128 split into 2 chunks of 64; 2-deep cp.async ring
// prefetches chunk s+1 (crossing tile boundaries) while computing chunk s.
// 256 threads, 8 warps (4x2), warp tile 32x64, mma.sync m16n8k16 bf16->fp32.
// ---------------------------------------------------------------------------
#define BK 64
#define LDT 72          // bf16 per smem row (144B stride; conflict-free ldmatrix)
#define TILE_BYTES (128 * LDT * 2)              // 18432 per matrix per slot
#define SMEM_BYTES (4 * TILE_BYTES)             // A[2] + B[2]

__device__ __forceinline__ unsigned smem_u32(const void* p) {
    return (unsigned)__cvta_generic_to_shared(p);
}
__device__ __forceinline__ void cp_async16(void* smem, const void* gmem) {
    asm volatile("cp.async.cg.shared.global [%0], [%1], 16;"
                 :: "r"(smem_u32(smem)), "l"(gmem));
}
__device__ __forceinline__ void ldsm_x4(unsigned r[4], unsigned addr) {
    asm volatile("ldmatrix.sync.aligned.m8n8.x4.shared.b16 {%0,%1,%2,%3}, [%4];"
                 : "=r"(r[0]), "=r"(r[1]), "=r"(r[2]), "=r"(r[3]) : "r"(addr));
}
__device__ __forceinline__ void mma16816(float c[4], const unsigned a[4],
                                         const unsigned b0, const unsigned b1) {
    asm volatile(
        "mma.sync.aligned.m16n8k16.row.col.f32.bf16.bf16.f32 "
        "{%0,%1,%2,%3}, {%4,%5,%6,%7}, {%8,%9}, {%0,%1,%2,%3};"
        : "+f"(c[0]), "+f"(c[1]), "+f"(c[2]), "+f"(c[3])
        : "r"(a[0]), "r"(a[1]), "r"(a[2]), "r"(a[3]), "r"(b0), "r"(b1));
}
__device__ __forceinline__ float neg_sqrt(float d2) {
    if (d2 <= 0.0f) return 0.0f;
    float r;
    asm("rsqrt.approx.f32 %0, %1;" : "=f"(r) : "f"(d2));
    return -(d2 * r);
}
__device__ __forceinline__ void st_cs_v2(float* p, float x, float y) {
    asm volatile("st.global.cs.v2.f32 [%0], {%1, %2};" :: "l"(p), "f"(x), "f"(y));
}

__global__ __launch_bounds__(256, 2)
void dist_gemm_kernel(float* __restrict__ out, int M, int nTiles, int nTileCol) {
    extern __shared__ char smem_raw[];
    // slot layout: A0 A1 B0 B1
    __nv_bfloat16 (*As)[128][LDT] =
        reinterpret_cast<__nv_bfloat16(*)[128][LDT]>(smem_raw);
    __nv_bfloat16 (*Bs)[128][LDT] =
        reinterpret_cast<__nv_bfloat16(*)[128][LDT]>(smem_raw + 2 * TILE_BYTES);

    const int tid  = threadIdx.x;
    const int lane = tid & 31;
    const int wid  = tid >> 5;          // 0..7
    const int wr   = wid & 3;           // warp row (x32)
    const int wc   = wid >> 2;          // warp col (x64)

    const int grid = gridDim.x;
    // local tiles: t = blockIdx.x + lt*grid;  steps: 2 per tile (k-chunks)
    const int nLocal = (nTiles - blockIdx.x + grid - 1) / grid;
    const int totalSteps = nLocal * 2;
    if (totalSteps <= 0) return;

    // per-thread load coords
    const int c  = tid & 7;             // uint4 col within 64-wide chunk
    const int r0 = tid >> 3;            // 0..31

    auto prefetch = [&](int s) {        // global step s -> (tile, chunk), slot = s&1
        const int lt = s >> 1, ch = s & 1, slot = s & 1;
        const int t = blockIdx.x + lt * grid;
        const int rowBase = (t / nTileCol) * 128;
        const int colBase = (t % nTileCol) * 128;
        const uint4* gA = reinterpret_cast<const uint4*>(g_Abf)
                          + (size_t)rowBase * 16 + ch * 8;
        const uint4* gB = reinterpret_cast<const uint4*>(g_Bbf)
                          + (size_t)colBase * 16 + ch * 8;
        #pragma unroll
        for (int p = 0; p < 4; p++) {
            const int r = p * 32 + r0;
            cp_async16(&As[slot][r][c * 8], &gA[(size_t)r * 16 + c]);
            cp_async16(&Bs[slot][r][c * 8], &gB[(size_t)r * 16 + c]);
        }
        asm volatile("cp.async.commit_group;");
    };

    prefetch(0);
    if (totalSteps > 1) prefetch(1);

    float acc[2][8][4];

    for (int s = 0; s < totalSteps; s++) {
        const int ch = s & 1, slot = s & 1;

        if (ch == 0) {
            #pragma unroll
            for (int i = 0; i < 2; i++)
                #pragma unroll
                for (int j = 0; j < 8; j++)
                    #pragma unroll
                    for (int k = 0; k < 4; k++)
                        acc[i][j][k] = 0.0f;
        }

        if (s + 1 < totalSteps)
            asm volatile("cp.async.wait_group 1;" ::: "memory");
        else
            asm volatile("cp.async.wait_group 0;" ::: "memory");
        __syncthreads();

        // ---- compute 4 k-steps of 16 on this chunk ----
        #pragma unroll
        for (int kk = 0; kk < 4; kk++) {
            unsigned afrag[2][4];
            #pragma unroll
            for (int mt = 0; mt < 2; mt++) {
                unsigned addr = smem_u32(
                    &As[slot][wr * 32 + mt * 16 + (lane & 15)][kk * 16 + (lane >> 4) * 8]);
                ldsm_x4(afrag[mt], addr);
            }
            unsigned bfrag[4][4];
            #pragma unroll
            for (int np = 0; np < 4; np++) {
                unsigned addr = smem_u32(
                    &Bs[slot][wc * 64 + np * 16 + (lane & 7) + ((lane >> 4) * 8)]
                             [kk * 16 + ((lane >> 3) & 1) * 8]);
                ldsm_x4(bfrag[np], addr);
            }
            #pragma unroll
            for (int mt = 0; mt < 2; mt++)
                #pragma unroll
                for (int np = 0; np < 4; np++) {
                    mma16816(acc[mt][np * 2 + 0], afrag[mt], bfrag[np][0], bfrag[np][1]);
                    mma16816(acc[mt][np * 2 + 1], afrag[mt], bfrag[np][2], bfrag[np][3]);
                }
        }
        __syncthreads();            // all warps done with this slot before overwrite

        if (s + 2 < totalSteps) prefetch(s + 2);   // overlaps epilogue + next compute

        if (ch == 1) {
            // ---- epilogue: -sqrt(max(a2 + b2 - 2ab, 0)), streaming stores ----
            const int t = blockIdx.x + (s >> 1) * grid;
            const int rowBase = (t / nTileCol) * 128;
            const int colBase = (t % nTileCol) * 128;
            const int g  = lane >> 2;
            const int cq = (lane & 3) * 2;
            #pragma unroll
            for (int mt = 0; mt < 2; mt++) {
                const int lr0 = wr * 32 + mt * 16 + g;
                const float a20 = __ldg(g_a2 + rowBase + lr0);
                const float a21 = __ldg(g_a2 + rowBase + lr0 + 8);
                const long long grow0 = rowBase + lr0;
                #pragma unroll
                for (int nt = 0; nt < 8; nt++) {
                    const int lc = wc * 64 + nt * 8 + cq;
                    const float b20 = __ldg(g_b2 + colBase + lc);
                    const float b21 = __ldg(g_b2 + colBase + lc + 1);
                    const int gcol = colBase + lc;

                    float d00 = fmaf(-2.0f, acc[mt][nt][0], a20 + b20);
                    float d01 = fmaf(-2.0f, acc[mt][nt][1], a20 + b21);
                    float d10 = fmaf(-2.0f, acc[mt][nt][2], a21 + b20);
                    float d11 = fmaf(-2.0f, acc[mt][nt][3], a21 + b21);

                    st_cs_v2(out + grow0 * M + gcol, neg_sqrt(d00), neg_sqrt(d01));
                    st_cs_v2(out + (grow0 + 8) * M + gcol, neg_sqrt(d10), neg_sqrt(d11));
                }
            }
        }
    }
}

// ---------------------------------------------------------------------------
extern "C" void kernel_launch(void* const* d_in, const int* in_sizes, int n_in,
                              void* d_out, int out_size) {
    const float* zA = (const float*)d_in[0];   // z_anc     [N, 128]
    const float* zB = (const float*)d_in[1];   // z_pos_neg [M, 128]
    const int N = in_sizes[0] / DMAX;
    const int M = in_sizes[1] / DMAX;

    const int totalWarps = N + M;
    prep_fused<<<(totalWarps * 32 + 255) / 256, 256>>>(zA, zB, N, M);

    int sms = 148;
    cudaDeviceGetAttribute(&sms, cudaDevAttrMultiProcessorCount, 0);

    cudaFuncSetAttribute(dist_gemm_kernel,
                         cudaFuncAttributeMaxDynamicSharedMemorySize, SMEM_BYTES);

    const int nTileCol = M / 128;
    const int nTiles = (N / 128) * nTileCol;
    int grid = 2 * sms;
    if (grid > nTiles) grid = nTiles;
    if (grid < 1) grid = 1;

    dist_gemm_kernel<<<grid, 256, SMEM_BYTES>>>((float*)d_out, M, nTiles, nTileCol);
}

// round 10
// speedup vs baseline: 1.0350x; 1.0350x over previous
#include <cuda_runtime.h>
#include <cuda_bf16.h>
#include <cstdint>

// Fixed problem shape: N = M = 8192, D = 128, fp32 in/out.
#define DMAX 128
#define NMAX 8192

// Scratch (device globals — no allocation allowed in kernel_launch)
__device__ __align__(16) __nv_bfloat16 g_Abf[NMAX * DMAX];
__device__ __align__(16) __nv_bfloat16 g_Bbf[NMAX * DMAX];
__device__ float g_a2[NMAX];
__device__ float g_b2[NMAX];

// ---------------------------------------------------------------------------
// Fused prep: one WARP per row across both matrices.
// ---------------------------------------------------------------------------
__global__ void prep_fused(const float* __restrict__ A, const float* __restrict__ B,
                           int N, int M) {
    const int warp = (blockIdx.x * blockDim.x + threadIdx.x) >> 5;
    const int lane = threadIdx.x & 31;
    if (warp >= N + M) return;

    const bool isA = warp < N;
    const int row = isA ? warp : warp - N;
    const float* src = (isA ? A : B) + (size_t)row * DMAX;

    float4 v = reinterpret_cast<const float4*>(src)[lane];

    __nv_bfloat162 lo = __floats2bfloat162_rn(v.x, v.y);
    __nv_bfloat162 hi = __floats2bfloat162_rn(v.z, v.w);
    uint2 packed = make_uint2(*reinterpret_cast<unsigned*>(&lo),
                              *reinterpret_cast<unsigned*>(&hi));
    __nv_bfloat16* dst = (isA ? g_Abf : g_Bbf) + (size_t)row * DMAX;
    reinterpret_cast<uint2*>(dst)[lane] = packed;

    float s = fmaf(v.x, v.x, fmaf(v.y, v.y, fmaf(v.z, v.z, v.w * v.w)));
    #pragma unroll
    for (int off = 16; off > 0; off >>= 1)
        s += __shfl_xor_sync(0xFFFFFFFFu, s, off);
    if (lane == 0) {
        if (isA) g_a2[row] = s;
        else     g_b2[row] = s;
    }
}

// ---------------------------------------------------------------------------
// Persistent pipelined GEMM + fused distance epilogue, occupancy-4 variant.
// CTA tile 128x64; K=128 in 2 chunks of 64; double-buffered cp.async.
// 256 threads, 8 warps (4x2), warp tile 32x32, mma.sync m16n8k16 bf16->fp32.
// 64 regs/thread target -> 4 CTAs/SM (32 warps/SM) to hide LDSM/HMMA latency.
// SMEM: 128B-row XOR swizzle (no padding): A slot 16KB + B slot 8KB, x2 slots.
// ---------------------------------------------------------------------------
#define SLOT_BYTES (128 * 128 + 64 * 128)   // A 16KB + B 8KB = 24576
#define B_OFF      (128 * 128)              // B offset within slot
#define SMEM_BYTES (2 * SLOT_BYTES)         // 49152

__device__ __forceinline__ unsigned smem_u32(const void* p) {
    return (unsigned)__cvta_generic_to_shared(p);
}
__device__ __forceinline__ unsigned swz(unsigned byte_off) {
    return byte_off ^ ((byte_off >> 3) & 0x70);
}
__device__ __forceinline__ void cp_async16(unsigned smem, const void* gmem) {
    asm volatile("cp.async.cg.shared.global [%0], [%1], 16;"
                 :: "r"(smem), "l"(gmem));
}
__device__ __forceinline__ void ldsm_x4(unsigned r[4], unsigned addr) {
    asm volatile("ldmatrix.sync.aligned.m8n8.x4.shared.b16 {%0,%1,%2,%3}, [%4];"
                 : "=r"(r[0]), "=r"(r[1]), "=r"(r[2]), "=r"(r[3]) : "r"(addr));
}
__device__ __forceinline__ void mma16816(float c[4], const unsigned a[4],
                                         const unsigned b0, const unsigned b1) {
    asm volatile(
        "mma.sync.aligned.m16n8k16.row.col.f32.bf16.bf16.f32 "
        "{%0,%1,%2,%3}, {%4,%5,%6,%7}, {%8,%9}, {%0,%1,%2,%3};"
        : "+f"(c[0]), "+f"(c[1]), "+f"(c[2]), "+f"(c[3])
        : "r"(a[0]), "r"(a[1]), "r"(a[2]), "r"(a[3]), "r"(b0), "r"(b1));
}
__device__ __forceinline__ float neg_sqrt(float d2) {
    if (d2 <= 0.0f) return 0.0f;
    float r;
    asm("rsqrt.approx.f32 %0, %1;" : "=f"(r) : "f"(d2));
    return -(d2 * r);
}
__device__ __forceinline__ void st_cs_v2(float* p, float x, float y) {
    asm volatile("st.global.cs.v2.f32 [%0], {%1, %2};" :: "l"(p), "f"(x), "f"(y));
}

__global__ __launch_bounds__(256, 4)
void dist_gemm_kernel(float* __restrict__ out, int M, int nTiles, int nTileCol) {
    extern __shared__ char smem_raw[];
    const unsigned sbase = smem_u32(smem_raw);

    const int tid  = threadIdx.x;
    const int lane = tid & 31;
    const int wid  = tid >> 5;          // 0..7
    const int wr   = wid & 3;           // warp row (x32)
    const int wc   = wid >> 2;          // warp col (x32)

    const int grid = gridDim.x;
    const int nLocal = (nTiles - blockIdx.x + grid - 1) / grid;
    if (nLocal <= 0) return;
    const int totalSteps = nLocal * 2;

    // per-thread load coords (8 uint4 per 64-wide K chunk row)
    const int c  = tid & 7;             // uint4 col within chunk
    const int r0 = tid >> 3;            // 0..31

    auto prefetch = [&](int s) {        // step s -> (tile, chunk), slot = s&1
        const int lt = s >> 1, ch = s & 1, slot = s & 1;
        const int t = blockIdx.x + lt * grid;
        const int rowBase = (t / nTileCol) * 128;
        const int colBase = (t % nTileCol) * 64;
        const unsigned aS = sbase + slot * SLOT_BYTES;
        const unsigned bS = aS + B_OFF;
        // A: 128 rows x 8 uint4 = 1024 -> 4 per thread
        #pragma unroll
        for (int p = 0; p < 4; p++) {
            const int r = p * 32 + r0;
            cp_async16(aS + swz(r * 128 + c * 16),
                       g_Abf + (size_t)(rowBase + r) * DMAX + ch * 64 + c * 8);
        }
        // B: 64 rows x 8 uint4 = 512 -> 2 per thread
        #pragma unroll
        for (int p = 0; p < 2; p++) {
            const int r = p * 32 + r0;
            cp_async16(bS + swz(r * 128 + c * 16),
                       g_Bbf + (size_t)(colBase + r) * DMAX + ch * 64 + c * 8);
        }
        asm volatile("cp.async.commit_group;");
    };

    prefetch(0);
    if (totalSteps > 1) prefetch(1);

    float acc[2][4][4];

    for (int s = 0; s < totalSteps; s++) {
        const int ch = s & 1, slot = s & 1;

        if (ch == 0) {
            #pragma unroll
            for (int i = 0; i < 2; i++)
                #pragma unroll
                for (int j = 0; j < 4; j++)
                    #pragma unroll
                    for (int k = 0; k < 4; k++)
                        acc[i][j][k] = 0.0f;
        }

        if (s + 1 < totalSteps)
            asm volatile("cp.async.wait_group 1;" ::: "memory");
        else
            asm volatile("cp.async.wait_group 0;" ::: "memory");
        __syncthreads();

        const unsigned aS = sbase + slot * SLOT_BYTES;
        const unsigned bS = aS + B_OFF;

        // ---- compute 4 k-steps of 16 on this chunk ----
        #pragma unroll
        for (int kk = 0; kk < 4; kk++) {
            unsigned afrag[2][4];
            #pragma unroll
            for (int mt = 0; mt < 2; mt++) {
                const int row = wr * 32 + mt * 16 + (lane & 15);
                ldsm_x4(afrag[mt], aS + swz(row * 128 + kk * 32 + (lane >> 4) * 16));
            }
            unsigned bfrag[2][4];
            #pragma unroll
            for (int np = 0; np < 2; np++) {
                const int row = wc * 32 + np * 16 + (lane & 7) + ((lane >> 4) * 8);
                ldsm_x4(bfrag[np], bS + swz(row * 128 + kk * 32 + ((lane >> 3) & 1) * 16));
            }
            #pragma unroll
            for (int mt = 0; mt < 2; mt++)
                #pragma unroll
                for (int np = 0; np < 2; np++) {
                    mma16816(acc[mt][np * 2 + 0], afrag[mt], bfrag[np][0], bfrag[np][1]);
                    mma16816(acc[mt][np * 2 + 1], afrag[mt], bfrag[np][2], bfrag[np][3]);
                }
        }
        __syncthreads();            // all warps done with this slot before overwrite

        if (s + 2 < totalSteps) prefetch(s + 2);

        if (ch == 1) {
            // ---- epilogue: -sqrt(max(a2 + b2 - 2ab, 0)), streaming stores ----
            const int t = blockIdx.x + (s >> 1) * grid;
            const int rowBase = (t / nTileCol) * 128;
            const int colBase = (t % nTileCol) * 64;
            const int g  = lane >> 2;
            const int cq = (lane & 3) * 2;
            #pragma unroll
            for (int mt = 0; mt < 2; mt++) {
                const int lr0 = wr * 32 + mt * 16 + g;
                const float a20 = __ldg(g_a2 + rowBase + lr0);
                const float a21 = __ldg(g_a2 + rowBase + lr0 + 8);
                const long long grow0 = rowBase + lr0;
                #pragma unroll
                for (int nt = 0; nt < 4; nt++) {
                    const int lc = wc * 32 + nt * 8 + cq;
                    const float b20 = __ldg(g_b2 + colBase + lc);
                    const float b21 = __ldg(g_b2 + colBase + lc + 1);
                    const int gcol = colBase + lc;

                    float d00 = fmaf(-2.0f, acc[mt][nt][0], a20 + b20);
                    float d01 = fmaf(-2.0f, acc[mt][nt][1], a20 + b21);
                    float d10 = fmaf(-2.0f, acc[mt][nt][2], a21 + b20);
                    float d11 = fmaf(-2.0f, acc[mt][nt][3], a21 + b21);

                    st_cs_v2(out + grow0 * M + gcol, neg_sqrt(d00), neg_sqrt(d01));
                    st_cs_v2(out + (grow0 + 8) * M + gcol, neg_sqrt(d10), neg_sqrt(d11));
                }
            }
        }
    }
}

// ---------------------------------------------------------------------------
extern "C" void kernel_launch(void* const* d_in, const int* in_sizes, int n_in,
                              void* d_out, int out_size) {
    const float* zA = (const float*)d_in[0];   // z_anc     [N, 128]
    const float* zB = (const float*)d_in[1];   // z_pos_neg [M, 128]
    const int N = in_sizes[0] / DMAX;
    const int M = in_sizes[1] / DMAX;

    const int totalWarps = N + M;
    prep_fused<<<(totalWarps * 32 + 255) / 256, 256>>>(zA, zB, N, M);

    int sms = 148;
    cudaDeviceGetAttribute(&sms, cudaDevAttrMultiProcessorCount, 0);

    cudaFuncSetAttribute(dist_gemm_kernel,
                         cudaFuncAttributeMaxDynamicSharedMemorySize, SMEM_BYTES);

    const int nTileCol = M / 64;
    const int nTiles = (N / 128) * nTileCol;
    int grid = 4 * sms;
    if (grid > nTiles) grid = nTiles;
    if (grid < 1) grid = 1;

    dist_gemm_kernel<<<grid, 256, SMEM_BYTES>>>((float*)d_out, M, nTiles, nTileCol);
}

// round 11
// speedup vs baseline: 1.1110x; 1.0734x over previous
#include <cuda_runtime.h>
#include <cuda_bf16.h>
#include <cstdint>

// Fixed problem shape: N = M = 8192, D = 128, fp32 in/out.
#define DMAX 128
#define NMAX 8192

// Scratch (device globals — no allocation allowed in kernel_launch)
__device__ __align__(16) __nv_bfloat16 g_Abf[NMAX * DMAX];
__device__ __align__(16) __nv_bfloat16 g_Bbf[NMAX * DMAX];
__device__ __align__(16) float g_a2[NMAX];
__device__ __align__(16) float g_b2[NMAX];

// ---------------------------------------------------------------------------
// Fused prep: one WARP per row across both matrices.
// ---------------------------------------------------------------------------
__global__ void prep_fused(const float* __restrict__ A, const float* __restrict__ B,
                           int N, int M) {
    const int warp = (blockIdx.x * blockDim.x + threadIdx.x) >> 5;
    const int lane = threadIdx.x & 31;
    if (warp >= N + M) return;

    const bool isA = warp < N;
    const int row = isA ? warp : warp - N;
    const float* src = (isA ? A : B) + (size_t)row * DMAX;

    float4 v = reinterpret_cast<const float4*>(src)[lane];

    __nv_bfloat162 lo = __floats2bfloat162_rn(v.x, v.y);
    __nv_bfloat162 hi = __floats2bfloat162_rn(v.z, v.w);
    uint2 packed = make_uint2(*reinterpret_cast<unsigned*>(&lo),
                              *reinterpret_cast<unsigned*>(&hi));
    __nv_bfloat16* dst = (isA ? g_Abf : g_Bbf) + (size_t)row * DMAX;
    reinterpret_cast<uint2*>(dst)[lane] = packed;

    float s = fmaf(v.x, v.x, fmaf(v.y, v.y, fmaf(v.z, v.z, v.w * v.w)));
    #pragma unroll
    for (int off = 16; off > 0; off >>= 1)
        s += __shfl_xor_sync(0xFFFFFFFFu, s, off);
    if (lane == 0) {
        if (isA) g_a2[row] = s;
        else     g_b2[row] = s;
    }
}

// ---------------------------------------------------------------------------
// Persistent strip-stationary GEMM + fused distance epilogue.
// Column-major contiguous tile ranges per CTA: B strip (64 cols x K128,
// 16KB smem) loaded once per ~14 tiles; A double-buffered by 64-wide K chunk.
// 256 threads, 8 warps (4x2), warp tile 32x32, mma.sync m16n8k16, occ 4.
// ldsm addresses strength-reduced: swz XOR mask is row-only, so
//   addr = base + (kk*32 ^ q), 1 LOP3 shared by all 4 ldsms per kk.
// ---------------------------------------------------------------------------
#define SMEM_BYTES 49152        // A0 16K @0, A1 16K @16384, B 16K @32768

__device__ __forceinline__ unsigned smem_u32(const void* p) {
    return (unsigned)__cvta_generic_to_shared(p);
}
__device__ __forceinline__ unsigned swz(unsigned byte_off) {
    return byte_off ^ ((byte_off >> 3) & 0x70);
}
__device__ __forceinline__ void cp_async16(unsigned smem, const void* gmem) {
    asm volatile("cp.async.cg.shared.global [%0], [%1], 16;"
                 :: "r"(smem), "l"(gmem));
}
__device__ __forceinline__ void ldsm_x4(unsigned r[4], unsigned addr) {
    asm volatile("ldmatrix.sync.aligned.m8n8.x4.shared.b16 {%0,%1,%2,%3}, [%4];"
                 : "=r"(r[0]), "=r"(r[1]), "=r"(r[2]), "=r"(r[3]) : "r"(addr));
}
__device__ __forceinline__ void mma16816(float c[4], const unsigned a[4],
                                         const unsigned b0, const unsigned b1) {
    asm volatile(
        "mma.sync.aligned.m16n8k16.row.col.f32.bf16.bf16.f32 "
        "{%0,%1,%2,%3}, {%4,%5,%6,%7}, {%8,%9}, {%0,%1,%2,%3};"
        : "+f"(c[0]), "+f"(c[1]), "+f"(c[2]), "+f"(c[3])
        : "r"(a[0]), "r"(a[1]), "r"(a[2]), "r"(a[3]), "r"(b0), "r"(b1));
}
__device__ __forceinline__ float neg_sqrt(float d2) {
    float dm = fmaxf(d2, 0.0f);          // FMNMX
    float s;
    asm("sqrt.approx.f32 %0, %1;" : "=f"(s) : "f"(dm));   // MUFU, sqrt(0)=0
    return __int_as_float(__float_as_int(s) | 0x80000000); // LOP3 sign flip
}
__device__ __forceinline__ void st_cs_v2(float* p, float x, float y) {
    asm volatile("st.global.cs.v2.f32 [%0], {%1, %2};" :: "l"(p), "f"(x), "f"(y));
}

__global__ __launch_bounds__(256, 4)
void dist_gemm_kernel(float* __restrict__ out, int M, int nTiles, int tpsShift) {
    extern __shared__ char smem_raw[];
    const unsigned sbase = smem_u32(smem_raw);
    const unsigned bBase = sbase + 32768;

    const int tid  = threadIdx.x;
    const int lane = tid & 31;
    const int wid  = tid >> 5;
    const int wr   = wid & 3;           // warp row (x32)
    const int wc   = wid >> 2;          // warp col (x32)

    // contiguous column-major tile range for this CTA
    int t0 = (int)((long long)blockIdx.x * nTiles / gridDim.x);
    int t1 = (int)(((long long)blockIdx.x + 1) * nTiles / gridDim.x);
    if (t0 >= t1) return;

    // ---- loader coords + precomputed swizzled smem offsets ----
    const int lc = tid & 7;             // 16B col within 64-wide chunk
    const int lr = tid >> 3;            // 0..31
    unsigned dstOff[4];
    #pragma unroll
    for (int p = 0; p < 4; p++)
        dstOff[p] = swz((unsigned)((p * 32 + lr) * 128 + lc * 16));

    // ---- ldsm address constants (swizzle strength reduction) ----
    const unsigned xa = (unsigned)(lane & 7) << 4;   // row-only XOR mask
    const unsigned qA = xa & 0x60;
    const unsigned pA = ((unsigned)(lane >> 4) << 4) ^ (xa & 0x10);
    const unsigned pB = ((unsigned)((lane >> 3) & 1) << 4) ^ (xa & 0x10);
    unsigned cbA[2], cbB[2];
    #pragma unroll
    for (int mt = 0; mt < 2; mt++)
        cbA[mt] = (unsigned)((wr * 32 + mt * 16 + (lane & 15)) * 128) + pA;
    #pragma unroll
    for (int np = 0; np < 2; np++)
        cbB[np] = (unsigned)((wc * 32 + np * 16 + (lane & 7) + ((lane >> 4) * 8)) * 128) + pB;

    const int g  = lane >> 2;           // epilogue row group
    const int cq = (lane & 3) * 2;      // epilogue col pair
    const int rtMask = (1 << tpsShift) - 1;

    int t = t0;
    while (t < t1) {
        const int strip = t >> tpsShift;
        int segEnd = (strip + 1) << tpsShift;
        if (segEnd > t1) segEnd = t1;
        const int colBase = strip * 64;
        const int steps = (segEnd - t) * 2;

        // ---- B strip load: 64 rows x K128 = 16KB, two 8KB K-halves ----
        #pragma unroll
        for (int ch = 0; ch < 2; ch++)
            #pragma unroll
            for (int p = 0; p < 2; p++)
                cp_async16(bBase + (unsigned)(ch * 8192) + dstOff[p],
                           g_Bbf + (size_t)(colBase + p * 32 + lr) * DMAX + ch * 64 + lc * 8);

        auto prefA = [&](int s) {       // A chunk prefetch; buffer = chunk parity
            const int tt = t + (s >> 1);
            const int ch = s & 1;
            const int rowBase = (tt & rtMask) << 7;
            const unsigned aDst = sbase + (unsigned)(ch * 16384);
            #pragma unroll
            for (int p = 0; p < 4; p++)
                cp_async16(aDst + dstOff[p],
                           g_Abf + (size_t)(rowBase + p * 32 + lr) * DMAX + ch * 64 + lc * 8);
            asm volatile("cp.async.commit_group;");
        };

        prefA(0);                       // group0 = B + A(t, ch0)
        if (steps > 1) prefA(1);        // group1 = A(t, ch1)

        float acc[2][4][4];

        for (int s = 0; s < steps; s++) {
            const int ch = s & 1;
            if (ch == 0) {
                #pragma unroll
                for (int i = 0; i < 2; i++)
                    #pragma unroll
                    for (int j = 0; j < 4; j++)
                        #pragma unroll
                        for (int k = 0; k < 4; k++)
                            acc[i][j][k] = 0.0f;
            }

            if (s + 1 < steps)
                asm volatile("cp.async.wait_group 1;" ::: "memory");
            else
                asm volatile("cp.async.wait_group 0;" ::: "memory");
            __syncthreads();

            const unsigned aCur = sbase + (unsigned)(ch * 16384);
            const unsigned bCur = bBase + (unsigned)(ch * 8192);

            #pragma unroll
            for (int kk = 0; kk < 4; kk++) {
                const unsigned colk = ((unsigned)(kk * 32)) ^ qA;  // 1 LOP3, shared
                unsigned afrag[2][4], bfrag[2][4];
                ldsm_x4(afrag[0], aCur + cbA[0] + colk);
                ldsm_x4(afrag[1], aCur + cbA[1] + colk);
                ldsm_x4(bfrag[0], bCur + cbB[0] + colk);
                ldsm_x4(bfrag[1], bCur + cbB[1] + colk);
                #pragma unroll
                for (int mt = 0; mt < 2; mt++)
                    #pragma unroll
                    for (int np = 0; np < 2; np++) {
                        mma16816(acc[mt][np * 2 + 0], afrag[mt], bfrag[np][0], bfrag[np][1]);
                        mma16816(acc[mt][np * 2 + 1], afrag[mt], bfrag[np][2], bfrag[np][3]);
                    }
            }
            __syncthreads();            // slot consumed by all warps

            if (s + 2 < steps) prefA(s + 2);

            if (ch == 1) {
                // ---- epilogue: -sqrt(max(a2 + b2 - 2ab, 0)) ----
                const int tt = t + (s >> 1);
                const int rowBase = (tt & rtMask) << 7;
                const float2* b2v =
                    reinterpret_cast<const float2*>(g_b2 + colBase + wc * 32);
                #pragma unroll
                for (int mt = 0; mt < 2; mt++) {
                    const int lr0 = wr * 32 + mt * 16 + g;
                    const float a20 = __ldg(g_a2 + rowBase + lr0);
                    const float a21 = __ldg(g_a2 + rowBase + lr0 + 8);
                    const long long grow0 = rowBase + lr0;
                    #pragma unroll
                    for (int nt = 0; nt < 4; nt++) {
                        const float2 b2 = __ldg(b2v + nt * 4 + (lane & 3));
                        const int gcol = colBase + wc * 32 + nt * 8 + cq;

                        float d00 = fmaf(-2.0f, acc[mt][nt][0], a20 + b2.x);
                        float d01 = fmaf(-2.0f, acc[mt][nt][1], a20 + b2.y);
                        float d10 = fmaf(-2.0f, acc[mt][nt][2], a21 + b2.x);
                        float d11 = fmaf(-2.0f, acc[mt][nt][3], a21 + b2.y);

                        st_cs_v2(out + grow0 * M + gcol, neg_sqrt(d00), neg_sqrt(d01));
                        st_cs_v2(out + (grow0 + 8) * M + gcol, neg_sqrt(d10), neg_sqrt(d11));
                    }
                }
            }
        }
        t = segEnd;
    }
}

// ---------------------------------------------------------------------------
extern "C" void kernel_launch(void* const* d_in, const int* in_sizes, int n_in,
                              void* d_out, int out_size) {
    const float* zA = (const float*)d_in[0];   // z_anc     [N, 128]
    const float* zB = (const float*)d_in[1];   // z_pos_neg [M, 128]
    const int N = in_sizes[0] / DMAX;
    const int M = in_sizes[1] / DMAX;

    const int totalWarps = N + M;
    prep_fused<<<(totalWarps * 32 + 255) / 256, 256>>>(zA, zB, N, M);

    int sms = 148;
    cudaDeviceGetAttribute(&sms, cudaDevAttrMultiProcessorCount, 0);

    cudaFuncSetAttribute(dist_gemm_kernel,
                         cudaFuncAttributeMaxDynamicSharedMemorySize, SMEM_BYTES);

    const int tps = N / 128;                   // row tiles per column strip
    int tpsShift = 0;
    while ((1 << tpsShift) < tps) tpsShift++;
    const int nTiles = (M / 64) * tps;         // column-major: strip * tps + rowTile

    int grid = 4 * sms;
    if (grid > nTiles) grid = nTiles;
    if (grid < 1) grid = 1;

    dist_gemm_kernel<<<grid, 256, SMEM_BYTES>>>((float*)d_out, M, nTiles, tpsShift);
}

// round 12
// speedup vs baseline: 1.2938x; 1.1646x over previous
#include <cuda_runtime.h>
#include <cuda_bf16.h>
#include <cstdint>

// Fixed problem shape: N = M = 8192, D = 128, fp32 in/out.
#define DMAX 128
#define NMAX 8192

// Scratch (device globals — no allocation allowed in kernel_launch)
__device__ __align__(16) __nv_bfloat16 g_Abf[NMAX * DMAX];
__device__ __align__(16) __nv_bfloat16 g_Bbf[NMAX * DMAX];
__device__ __align__(16) float g_a2[NMAX];
__device__ __align__(16) float g_b2[NMAX];

// ---------------------------------------------------------------------------
// Fused prep: one WARP per row across both matrices.
// ---------------------------------------------------------------------------
__global__ void prep_fused(const float* __restrict__ A, const float* __restrict__ B,
                           int N, int M) {
    const int warp = (blockIdx.x * blockDim.x + threadIdx.x) >> 5;
    const int lane = threadIdx.x & 31;
    if (warp >= N + M) return;

    const bool isA = warp < N;
    const int row = isA ? warp : warp - N;
    const float* src = (isA ? A : B) + (size_t)row * DMAX;

    float4 v = reinterpret_cast<const float4*>(src)[lane];

    __nv_bfloat162 lo = __floats2bfloat162_rn(v.x, v.y);
    __nv_bfloat162 hi = __floats2bfloat162_rn(v.z, v.w);
    uint2 packed = make_uint2(*reinterpret_cast<unsigned*>(&lo),
                              *reinterpret_cast<unsigned*>(&hi));
    __nv_bfloat16* dst = (isA ? g_Abf : g_Bbf) + (size_t)row * DMAX;
    reinterpret_cast<uint2*>(dst)[lane] = packed;

    float s = fmaf(v.x, v.x, fmaf(v.y, v.y, fmaf(v.z, v.z, v.w * v.w)));
    #pragma unroll
    for (int off = 16; off > 0; off >>= 1)
        s += __shfl_xor_sync(0xFFFFFFFFu, s, off);
    if (lane == 0) {
        if (isA) g_a2[row] = s;
        else     g_b2[row] = s;
    }
}

// ---------------------------------------------------------------------------
// Persistent strip-stationary GEMM + fused distance epilogue.
// CTA tile 128x128 (rows x cols), warp tile 32x64, 8 warps (4x2), occ 2.
// B strip: 128 cols x K128 = 32KB smem, loaded once per strip (~64 tiles).
// A: 64-wide K chunks, 3 buffers x 16KB, cp.async pipeline depth 3.
// ldsm swizzle strength-reduced (XOR mask row-only, 1 LOP3/kk).
// L1 traffic: ~18B/output vs 24.5 in the 32x32 variant.
// ---------------------------------------------------------------------------
#define SMEM_BYTES (3 * 16384 + 32768)   // A0,A1,A2 + B = 81920

__device__ __forceinline__ unsigned smem_u32(const void* p) {
    return (unsigned)__cvta_generic_to_shared(p);
}
__device__ __forceinline__ unsigned swz(unsigned byte_off) {
    return byte_off ^ ((byte_off >> 3) & 0x70);
}
__device__ __forceinline__ void cp_async16(unsigned smem, const void* gmem) {
    asm volatile("cp.async.cg.shared.global [%0], [%1], 16;"
                 :: "r"(smem), "l"(gmem));
}
__device__ __forceinline__ void ldsm_x4(unsigned r[4], unsigned addr) {
    asm volatile("ldmatrix.sync.aligned.m8n8.x4.shared.b16 {%0,%1,%2,%3}, [%4];"
                 : "=r"(r[0]), "=r"(r[1]), "=r"(r[2]), "=r"(r[3]) : "r"(addr));
}
__device__ __forceinline__ void mma16816(float c[4], const unsigned a[4],
                                         const unsigned b0, const unsigned b1) {
    asm volatile(
        "mma.sync.aligned.m16n8k16.row.col.f32.bf16.bf16.f32 "
        "{%0,%1,%2,%3}, {%4,%5,%6,%7}, {%8,%9}, {%0,%1,%2,%3};"
        : "+f"(c[0]), "+f"(c[1]), "+f"(c[2]), "+f"(c[3])
        : "r"(a[0]), "r"(a[1]), "r"(a[2]), "r"(a[3]), "r"(b0), "r"(b1));
}
__device__ __forceinline__ float neg_sqrt(float d2) {
    float dm = fmaxf(d2, 0.0f);
    float s;
    asm("sqrt.approx.f32 %0, %1;" : "=f"(s) : "f"(dm));
    return __int_as_float(__float_as_int(s) | 0x80000000);
}
__device__ __forceinline__ void st_cs_v2(float* p, float x, float y) {
    asm volatile("st.global.cs.v2.f32 [%0], {%1, %2};" :: "l"(p), "f"(x), "f"(y));
}

__global__ __launch_bounds__(256, 2)
void dist_gemm_kernel(float* __restrict__ out, int M, int nTiles, int tpsShift) {
    extern __shared__ char smem_raw[];
    const unsigned sbase = smem_u32(smem_raw);
    const unsigned bBase = sbase + 49152;

    const int tid  = threadIdx.x;
    const int lane = tid & 31;
    const int wid  = tid >> 5;
    const int wr   = wid & 3;           // warp row (x32)
    const int wc   = wid >> 2;          // warp col (x64)

    // contiguous column-major tile range for this CTA
    int t0 = (int)((long long)blockIdx.x * nTiles / gridDim.x);
    int t1 = (int)(((long long)blockIdx.x + 1) * nTiles / gridDim.x);
    if (t0 >= t1) return;

    // ---- loader coords + precomputed swizzled smem offsets ----
    const int lc = tid & 7;             // 16B col within 64-wide chunk
    const int lr = tid >> 3;            // 0..31
    unsigned dstOff[4];
    #pragma unroll
    for (int p = 0; p < 4; p++)
        dstOff[p] = swz((unsigned)((p * 32 + lr) * 128 + lc * 16));

    // ---- ldsm address constants (swizzle strength reduction) ----
    const unsigned xa = (unsigned)(lane & 7) << 4;   // row-only XOR mask
    const unsigned qA = xa & 0x60;
    const unsigned pA = ((unsigned)(lane >> 4) << 4) ^ (xa & 0x10);
    const unsigned pB = ((unsigned)((lane >> 3) & 1) << 4) ^ (xa & 0x10);
    unsigned cbA[2], cbB[4];
    #pragma unroll
    for (int mt = 0; mt < 2; mt++)
        cbA[mt] = (unsigned)((wr * 32 + mt * 16 + (lane & 15)) * 128) + pA;
    #pragma unroll
    for (int np = 0; np < 4; np++)
        cbB[np] = (unsigned)((wc * 64 + np * 16 + (lane & 7) + ((lane >> 4) * 8)) * 128) + pB;

    const int g  = lane >> 2;           // epilogue row group
    const int cq = (lane & 3) * 2;      // epilogue col pair
    const int rtMask = (1 << tpsShift) - 1;

    int t = t0;
    while (t < t1) {
        const int strip = t >> tpsShift;
        int segEnd = (strip + 1) << tpsShift;
        if (segEnd > t1) segEnd = t1;
        const int colBase = strip * 128;
        const int steps = (segEnd - t) * 2;

        // ---- B strip load: 128 rows x K128 = 32KB, two 16KB K-halves ----
        #pragma unroll
        for (int ch = 0; ch < 2; ch++)
            #pragma unroll
            for (int p = 0; p < 4; p++)
                cp_async16(bBase + (unsigned)(ch * 16384) + dstOff[p],
                           g_Bbf + (size_t)(colBase + p * 32 + lr) * DMAX + ch * 64 + lc * 8);

        auto prefA = [&](int s) {       // A chunk prefetch; buffer = s % 3
            const int tt = t + (s >> 1);
            const int ch = s & 1;
            const int rowBase = (tt & rtMask) << 7;
            const unsigned aDst = sbase + (unsigned)((s % 3) * 16384);
            #pragma unroll
            for (int p = 0; p < 4; p++)
                cp_async16(aDst + dstOff[p],
                           g_Abf + (size_t)(rowBase + p * 32 + lr) * DMAX + ch * 64 + lc * 8);
            asm volatile("cp.async.commit_group;");
        };

        prefA(0);                       // group0 = B + A chunk 0
        if (steps > 1) prefA(1);
        if (steps > 2) prefA(2);

        float acc[2][8][4];

        for (int s = 0; s < steps; s++) {
            const int ch = s & 1;
            if (ch == 0) {
                #pragma unroll
                for (int i = 0; i < 2; i++)
                    #pragma unroll
                    for (int j = 0; j < 8; j++)
                        #pragma unroll
                        for (int k = 0; k < 4; k++)
                            acc[i][j][k] = 0.0f;
            }

            const int remain = steps - 1 - s;   // groups still outstanding after this
            if (remain >= 2)
                asm volatile("cp.async.wait_group 2;" ::: "memory");
            else if (remain == 1)
                asm volatile("cp.async.wait_group 1;" ::: "memory");
            else
                asm volatile("cp.async.wait_group 0;" ::: "memory");
            __syncthreads();

            const unsigned aCur = sbase + (unsigned)((s % 3) * 16384);
            const unsigned bCur = bBase + (unsigned)(ch * 16384);

            #pragma unroll
            for (int kk = 0; kk < 4; kk++) {
                const unsigned colk = ((unsigned)(kk * 32)) ^ qA;  // 1 LOP3, shared
                unsigned afrag[2][4], bfrag[4][4];
                ldsm_x4(afrag[0], aCur + cbA[0] + colk);
                ldsm_x4(afrag[1], aCur + cbA[1] + colk);
                #pragma unroll
                for (int np = 0; np < 4; np++)
                    ldsm_x4(bfrag[np], bCur + cbB[np] + colk);
                #pragma unroll
                for (int mt = 0; mt < 2; mt++)
                    #pragma unroll
                    for (int np = 0; np < 4; np++) {
                        mma16816(acc[mt][np * 2 + 0], afrag[mt], bfrag[np][0], bfrag[np][1]);
                        mma16816(acc[mt][np * 2 + 1], afrag[mt], bfrag[np][2], bfrag[np][3]);
                    }
            }
            __syncthreads();            // slot consumed by all warps

            if (s + 3 < steps) prefA(s + 3);

            if (ch == 1) {
                // ---- epilogue: -sqrt(max(a2 + b2 - 2ab, 0)) ----
                const int tt = t + (s >> 1);
                const int rowBase = (tt & rtMask) << 7;
                const float2* b2v =
                    reinterpret_cast<const float2*>(g_b2 + colBase + wc * 64);
                #pragma unroll
                for (int mt = 0; mt < 2; mt++) {
                    const int lr0 = wr * 32 + mt * 16 + g;
                    const float a20 = __ldg(g_a2 + rowBase + lr0);
                    const float a21 = __ldg(g_a2 + rowBase + lr0 + 8);
                    const long long grow0 = rowBase + lr0;
                    #pragma unroll
                    for (int nt = 0; nt < 8; nt++) {
                        const float2 b2 = __ldg(b2v + nt * 4 + (lane & 3));
                        const int gcol = colBase + wc * 64 + nt * 8 + cq;

                        float d00 = fmaf(-2.0f, acc[mt][nt][0], a20 + b2.x);
                        float d01 = fmaf(-2.0f, acc[mt][nt][1], a20 + b2.y);
                        float d10 = fmaf(-2.0f, acc[mt][nt][2], a21 + b2.x);
                        float d11 = fmaf(-2.0f, acc[mt][nt][3], a21 + b2.y);

                        st_cs_v2(out + grow0 * M + gcol, neg_sqrt(d00), neg_sqrt(d01));
                        st_cs_v2(out + (grow0 + 8) * M + gcol, neg_sqrt(d10), neg_sqrt(d11));
                    }
                }
            }
        }
        t = segEnd;
    }
}

// ---------------------------------------------------------------------------
extern "C" void kernel_launch(void* const* d_in, const int* in_sizes, int n_in,
                              void* d_out, int out_size) {
    const float* zA = (const float*)d_in[0];   // z_anc     [N, 128]
    const float* zB = (const float*)d_in[1];   // z_pos_neg [M, 128]
    const int N = in_sizes[0] / DMAX;
    const int M = in_sizes[1] / DMAX;

    const int totalWarps = N + M;
    prep_fused<<<(totalWarps * 32 + 255) / 256, 256>>>(zA, zB, N, M);

    int sms = 148;
    cudaDeviceGetAttribute(&sms, cudaDevAttrMultiProcessorCount, 0);

    cudaFuncSetAttribute(dist_gemm_kernel,
                         cudaFuncAttributeMaxDynamicSharedMemorySize, SMEM_BYTES);

    const int tps = N / 128;                   // row tiles per column strip
    int tpsShift = 0;
    while ((1 << tpsShift) < tps) tpsShift++;
    const int nTiles = (M / 128) * tps;        // column-major: strip * tps + rowTile

    int grid = 2 * sms;
    if (grid > nTiles) grid = nTiles;
    if (grid < 1) grid = 1;

    dist_gemm_kernel<<<grid, 256, SMEM_BYTES>>>((float*)d_out, M, nTiles, tpsShift);
}

// round 13
// speedup vs baseline: 1.4405x; 1.1134x over previous
#include <cuda_runtime.h>
#include <cuda_bf16.h>
#include <cstdint>

// Fixed problem shape: N = M = 8192, D = 128, fp32 in/out.
#define DMAX 128
#define NMAX 8192

// Scratch (device globals — no allocation allowed in kernel_launch)
__device__ __align__(16) __nv_bfloat16 g_Abf[NMAX * DMAX];
__device__ __align__(16) __nv_bfloat16 g_Bbf[NMAX * DMAX];
__device__ __align__(16) float g_a2[NMAX];
__device__ __align__(16) float g_b2[NMAX];

// ---------------------------------------------------------------------------
// Fused prep: one WARP per row across both matrices.
// ---------------------------------------------------------------------------
__global__ void prep_fused(const float* __restrict__ A, const float* __restrict__ B,
                           int N, int M) {
    const int warp = (blockIdx.x * blockDim.x + threadIdx.x) >> 5;
    const int lane = threadIdx.x & 31;
    if (warp >= N + M) return;

    const bool isA = warp < N;
    const int row = isA ? warp : warp - N;
    const float* src = (isA ? A : B) + (size_t)row * DMAX;

    float4 v = reinterpret_cast<const float4*>(src)[lane];

    __nv_bfloat162 lo = __floats2bfloat162_rn(v.x, v.y);
    __nv_bfloat162 hi = __floats2bfloat162_rn(v.z, v.w);
    uint2 packed = make_uint2(*reinterpret_cast<unsigned*>(&lo),
                              *reinterpret_cast<unsigned*>(&hi));
    __nv_bfloat16* dst = (isA ? g_Abf : g_Bbf) + (size_t)row * DMAX;
    reinterpret_cast<uint2*>(dst)[lane] = packed;

    float s = fmaf(v.x, v.x, fmaf(v.y, v.y, fmaf(v.z, v.z, v.w * v.w)));
    #pragma unroll
    for (int off = 16; off > 0; off >>= 1)
        s += __shfl_xor_sync(0xFFFFFFFFu, s, off);
    if (lane == 0) {
        if (isA) g_a2[row] = s;
        else     g_b2[row] = s;
    }
}

// ---------------------------------------------------------------------------
// Persistent strip-stationary GEMM + fused distance epilogue.
// CTA tile 128x128, 4 warps (2x2), warp tile 64x64 -> 8 B/out LDSM traffic
// (vs 12 for 32x64). 128 threads, launch_bounds(128,2): ~190 regs, no spill,
// 2 CTAs/SM. B strip 32KB stationary per strip; A 64-wide K chunks,
// 3 buffers x 16KB, cp.async pipeline depth 3.
// ldsm swizzle strength-reduced (XOR mask row-only, 1 LOP3/kk).
// ---------------------------------------------------------------------------
#define SMEM_BYTES (3 * 16384 + 32768)   // A0,A1,A2 + B = 81920

__device__ __forceinline__ unsigned smem_u32(const void* p) {
    return (unsigned)__cvta_generic_to_shared(p);
}
__device__ __forceinline__ unsigned swz(unsigned byte_off) {
    return byte_off ^ ((byte_off >> 3) & 0x70);
}
__device__ __forceinline__ void cp_async16(unsigned smem, const void* gmem) {
    asm volatile("cp.async.cg.shared.global [%0], [%1], 16;"
                 :: "r"(smem), "l"(gmem));
}
__device__ __forceinline__ void ldsm_x4(unsigned r[4], unsigned addr) {
    asm volatile("ldmatrix.sync.aligned.m8n8.x4.shared.b16 {%0,%1,%2,%3}, [%4];"
                 : "=r"(r[0]), "=r"(r[1]), "=r"(r[2]), "=r"(r[3]) : "r"(addr));
}
__device__ __forceinline__ void mma16816(float c[4], const unsigned a[4],
                                         const unsigned b0, const unsigned b1) {
    asm volatile(
        "mma.sync.aligned.m16n8k16.row.col.f32.bf16.bf16.f32 "
        "{%0,%1,%2,%3}, {%4,%5,%6,%7}, {%8,%9}, {%0,%1,%2,%3};"
        : "+f"(c[0]), "+f"(c[1]), "+f"(c[2]), "+f"(c[3])
        : "r"(a[0]), "r"(a[1]), "r"(a[2]), "r"(a[3]), "r"(b0), "r"(b1));
}
__device__ __forceinline__ float neg_sqrt(float d2) {
    float dm = fmaxf(d2, 0.0f);
    float s;
    asm("sqrt.approx.f32 %0, %1;" : "=f"(s) : "f"(dm));
    return __int_as_float(__float_as_int(s) | 0x80000000);
}
__device__ __forceinline__ void st_cs_v2(float* p, float x, float y) {
    asm volatile("st.global.cs.v2.f32 [%0], {%1, %2};" :: "l"(p), "f"(x), "f"(y));
}

__global__ __launch_bounds__(128, 2)
void dist_gemm_kernel(float* __restrict__ out, int M, int nTiles, int tpsShift) {
    extern __shared__ char smem_raw[];
    const unsigned sbase = smem_u32(smem_raw);
    const unsigned bBase = sbase + 49152;

    const int tid  = threadIdx.x;
    const int lane = tid & 31;
    const int wid  = tid >> 5;          // 0..3
    const int wr   = wid & 1;           // warp row (x64)
    const int wc   = wid >> 1;          // warp col (x64)

    // contiguous column-major tile range for this CTA
    int t0 = (int)((long long)blockIdx.x * nTiles / gridDim.x);
    int t1 = (int)(((long long)blockIdx.x + 1) * nTiles / gridDim.x);
    if (t0 >= t1) return;

    // ---- loader coords + precomputed swizzled smem offsets ----
    const int lc = tid & 7;             // 16B col within 64-wide chunk
    const int lr = tid >> 3;            // 0..15
    unsigned dstOff[8];
    #pragma unroll
    for (int p = 0; p < 8; p++)
        dstOff[p] = swz((unsigned)((p * 16 + lr) * 128 + lc * 16));

    // ---- ldsm address constants (swizzle strength reduction) ----
    const unsigned xa = (unsigned)(lane & 7) << 4;   // row-only XOR mask
    const unsigned qA = xa & 0x60;
    const unsigned pA = ((unsigned)(lane >> 4) << 4) ^ (xa & 0x10);
    const unsigned pB = ((unsigned)((lane >> 3) & 1) << 4) ^ (xa & 0x10);
    unsigned cbA[4], cbB[4];
    #pragma unroll
    for (int mt = 0; mt < 4; mt++)
        cbA[mt] = (unsigned)((wr * 64 + mt * 16 + (lane & 15)) * 128) + pA;
    #pragma unroll
    for (int np = 0; np < 4; np++)
        cbB[np] = (unsigned)((wc * 64 + np * 16 + (lane & 7) + ((lane >> 4) * 8)) * 128) + pB;

    const int g  = lane >> 2;           // epilogue row group
    const int cq = (lane & 3) * 2;      // epilogue col pair
    const int rtMask = (1 << tpsShift) - 1;

    int t = t0;
    while (t < t1) {
        const int strip = t >> tpsShift;
        int segEnd = (strip + 1) << tpsShift;
        if (segEnd > t1) segEnd = t1;
        const int colBase = strip * 128;
        const int steps = (segEnd - t) * 2;

        // ---- B strip load: 128 rows x K128 = 32KB, two 16KB K-halves ----
        #pragma unroll
        for (int ch = 0; ch < 2; ch++)
            #pragma unroll
            for (int p = 0; p < 8; p++)
                cp_async16(bBase + (unsigned)(ch * 16384) + dstOff[p],
                           g_Bbf + (size_t)(colBase + p * 16 + lr) * DMAX + ch * 64 + lc * 8);

        auto prefA = [&](int s) {       // A chunk prefetch; buffer = s % 3
            const int tt = t + (s >> 1);
            const int ch = s & 1;
            const int rowBase = (tt & rtMask) << 7;
            const unsigned aDst = sbase + (unsigned)((s % 3) * 16384);
            #pragma unroll
            for (int p = 0; p < 8; p++)
                cp_async16(aDst + dstOff[p],
                           g_Abf + (size_t)(rowBase + p * 16 + lr) * DMAX + ch * 64 + lc * 8);
            asm volatile("cp.async.commit_group;");
        };

        prefA(0);                       // group0 = B + A chunk 0
        if (steps > 1) prefA(1);
        if (steps > 2) prefA(2);

        float acc[4][8][4];

        for (int s = 0; s < steps; s++) {
            const int ch = s & 1;
            if (ch == 0) {
                #pragma unroll
                for (int i = 0; i < 4; i++)
                    #pragma unroll
                    for (int j = 0; j < 8; j++)
                        #pragma unroll
                        for (int k = 0; k < 4; k++)
                            acc[i][j][k] = 0.0f;
            }

            const int remain = steps - 1 - s;   // groups still outstanding after this
            if (remain >= 2)
                asm volatile("cp.async.wait_group 2;" ::: "memory");
            else if (remain == 1)
                asm volatile("cp.async.wait_group 1;" ::: "memory");
            else
                asm volatile("cp.async.wait_group 0;" ::: "memory");
            __syncthreads();

            const unsigned aCur = sbase + (unsigned)((s % 3) * 16384);
            const unsigned bCur = bBase + (unsigned)(ch * 16384);

            #pragma unroll
            for (int kk = 0; kk < 4; kk++) {
                const unsigned colk = ((unsigned)(kk * 32)) ^ qA;  // 1 LOP3, shared
                unsigned afrag[4][4], bfrag[4][4];
                #pragma unroll
                for (int mt = 0; mt < 4; mt++)
                    ldsm_x4(afrag[mt], aCur + cbA[mt] + colk);
                #pragma unroll
                for (int np = 0; np < 4; np++)
                    ldsm_x4(bfrag[np], bCur + cbB[np] + colk);
                #pragma unroll
                for (int mt = 0; mt < 4; mt++)
                    #pragma unroll
                    for (int np = 0; np < 4; np++) {
                        mma16816(acc[mt][np * 2 + 0], afrag[mt], bfrag[np][0], bfrag[np][1]);
                        mma16816(acc[mt][np * 2 + 1], afrag[mt], bfrag[np][2], bfrag[np][3]);
                    }
            }
            __syncthreads();            // slot consumed by all warps

            if (s + 3 < steps) prefA(s + 3);

            if (ch == 1) {
                // ---- epilogue: -sqrt(max(a2 + b2 - 2ab, 0)) ----
                const int tt = t + (s >> 1);
                const int rowBase = (tt & rtMask) << 7;
                const float2* b2v =
                    reinterpret_cast<const float2*>(g_b2 + colBase + wc * 64);
                #pragma unroll
                for (int mt = 0; mt < 4; mt++) {
                    const int lr0 = wr * 64 + mt * 16 + g;
                    const float a20 = __ldg(g_a2 + rowBase + lr0);
                    const float a21 = __ldg(g_a2 + rowBase + lr0 + 8);
                    const long long grow0 = rowBase + lr0;
                    #pragma unroll
                    for (int nt = 0; nt < 8; nt++) {
                        const float2 b2 = __ldg(b2v + nt * 4 + (lane & 3));
                        const int gcol = colBase + wc * 64 + nt * 8 + cq;

                        float d00 = fmaf(-2.0f, acc[mt][nt][0], a20 + b2.x);
                        float d01 = fmaf(-2.0f, acc[mt][nt][1], a20 + b2.y);
                        float d10 = fmaf(-2.0f, acc[mt][nt][2], a21 + b2.x);
                        float d11 = fmaf(-2.0f, acc[mt][nt][3], a21 + b2.y);

                        st_cs_v2(out + grow0 * M + gcol, neg_sqrt(d00), neg_sqrt(d01));
                        st_cs_v2(out + (grow0 + 8) * M + gcol, neg_sqrt(d10), neg_sqrt(d11));
                    }
                }
            }
        }
        t = segEnd;
    }
}

// ---------------------------------------------------------------------------
extern "C" void kernel_launch(void* const* d_in, const int* in_sizes, int n_in,
                              void* d_out, int out_size) {
    const float* zA = (const float*)d_in[0];   // z_anc     [N, 128]
    const float* zB = (const float*)d_in[1];   // z_pos_neg [M, 128]
    const int N = in_sizes[0] / DMAX;
    const int M = in_sizes[1] / DMAX;

    const int totalWarps = N + M;
    prep_fused<<<(totalWarps * 32 + 255) / 256, 256>>>(zA, zB, N, M);

    int sms = 148;
    cudaDeviceGetAttribute(&sms, cudaDevAttrMultiProcessorCount, 0);

    cudaFuncSetAttribute(dist_gemm_kernel,
                         cudaFuncAttributeMaxDynamicSharedMemorySize, SMEM_BYTES);

    const int tps = N / 128;                   // row tiles per column strip
    int tpsShift = 0;
    while ((1 << tpsShift) < tps) tpsShift++;
    const int nTiles = (M / 128) * tps;        // column-major: strip * tps + rowTile

    int grid = 2 * sms;
    if (grid > nTiles) grid = nTiles;
    if (grid < 1) grid = 1;

    dist_gemm_kernel<<<grid, 128, SMEM_BYTES>>>((float*)d_out, M, nTiles, tpsShift);
}

// round 15
// speedup vs baseline: 1.4466x; 1.0042x over previous
#include <cuda_runtime.h>
#include <cuda_bf16.h>
#include <cstdint>

// Fixed problem shape: N = M = 8192, D = 128, fp32 in/out.
#define DMAX 128
#define NMAX 8192

// Scratch (device globals — no allocation allowed in kernel_launch)
__device__ __align__(16) __nv_bfloat16 g_Abf[NMAX * DMAX];
__device__ __align__(16) __nv_bfloat16 g_Bbf[NMAX * DMAX];
__device__ __align__(16) float g_a2[NMAX];
__device__ __align__(16) float g_b2[NMAX];

// ---------------------------------------------------------------------------
// Fused prep: one WARP per row across both matrices.
// ---------------------------------------------------------------------------
__global__ void prep_fused(const float* __restrict__ A, const float* __restrict__ B,
                           int N, int M) {
    const int warp = (blockIdx.x * blockDim.x + threadIdx.x) >> 5;
    const int lane = threadIdx.x & 31;
    if (warp >= N + M) return;

    const bool isA = warp < N;
    const int row = isA ? warp : warp - N;
    const float* src = (isA ? A : B) + (size_t)row * DMAX;

    float4 v = reinterpret_cast<const float4*>(src)[lane];

    __nv_bfloat162 lo = __floats2bfloat162_rn(v.x, v.y);
    __nv_bfloat162 hi = __floats2bfloat162_rn(v.z, v.w);
    uint2 packed = make_uint2(*reinterpret_cast<unsigned*>(&lo),
                              *reinterpret_cast<unsigned*>(&hi));
    __nv_bfloat16* dst = (isA ? g_Abf : g_Bbf) + (size_t)row * DMAX;
    reinterpret_cast<uint2*>(dst)[lane] = packed;

    float s = fmaf(v.x, v.x, fmaf(v.y, v.y, fmaf(v.z, v.z, v.w * v.w)));
    #pragma unroll
    for (int off = 16; off > 0; off >>= 1)
        s += __shfl_xor_sync(0xFFFFFFFFu, s, off);
    if (lane == 0) {
        if (isA) g_a2[row] = s;
        else     g_b2[row] = s;
    }
}

// ---------------------------------------------------------------------------
// Persistent strip-stationary GEMM + fused distance epilogue.
// CTA tile 128x128, 4 warps (2x2), warp tile 64x64 (8 B/out LDSM traffic).
// 128 threads, launch_bounds(128,2), 2 CTAs/SM.
// B strip 32KB stationary per strip; A 64-wide K chunks, 4 buffers x 16KB,
// cp.async pipeline depth 3 -> ONE barrier per step: with 4 buffers,
// prefA(s+3) writes (s+3)&3 != s&3, so the post-compute barrier is dropped;
// slot-reuse safety comes from the next step's entry barrier.
// ldsm swizzle strength-reduced (XOR mask row-only, 1 LOP3/kk).
// ---------------------------------------------------------------------------
#define SMEM_BYTES (4 * 16384 + 32768)   // A0..A3 + B = 98304 (96KB)

__device__ __forceinline__ unsigned smem_u32(const void* p) {
    return (unsigned)__cvta_generic_to_shared(p);
}
__device__ __forceinline__ unsigned swz(unsigned byte_off) {
    return byte_off ^ ((byte_off >> 3) & 0x70);
}
__device__ __forceinline__ void cp_async16(unsigned smem, const void* gmem) {
    asm volatile("cp.async.cg.shared.global [%0], [%1], 16;"
                 :: "r"(smem), "l"(gmem));
}
__device__ __forceinline__ void ldsm_x4(unsigned r[4], unsigned addr) {
    asm volatile("ldmatrix.sync.aligned.m8n8.x4.shared.b16 {%0,%1,%2,%3}, [%4];"
                 : "=r"(r[0]), "=r"(r[1]), "=r"(r[2]), "=r"(r[3]) : "r"(addr));
}
__device__ __forceinline__ void mma16816(float c[4], const unsigned a[4],
                                         const unsigned b0, const unsigned b1) {
    asm volatile(
        "mma.sync.aligned.m16n8k16.row.col.f32.bf16.bf16.f32 "
        "{%0,%1,%2,%3}, {%4,%5,%6,%7}, {%8,%9}, {%0,%1,%2,%3};"
        : "+f"(c[0]), "+f"(c[1]), "+f"(c[2]), "+f"(c[3])
        : "r"(a[0]), "r"(a[1]), "r"(a[2]), "r"(a[3]), "r"(b0), "r"(b1));
}
__device__ __forceinline__ float neg_sqrt(float d2) {
    float dm = fmaxf(d2, 0.0f);
    float s;
    asm("sqrt.approx.f32 %0, %1;" : "=f"(s) : "f"(dm));
    return __int_as_float(__float_as_int(s) | 0x80000000);
}
__device__ __forceinline__ void st_cs_v2(float* p, float x, float y) {
    asm volatile("st.global.cs.v2.f32 [%0], {%1, %2};" :: "l"(p), "f"(x), "f"(y));
}

__global__ __launch_bounds__(128, 2)
void dist_gemm_kernel(float* __restrict__ out, int M, int nTiles, int tpsShift) {
    extern __shared__ char smem_raw[];
    const unsigned sbase = smem_u32(smem_raw);
    const unsigned bBase = sbase + 65536;

    const int tid  = threadIdx.x;
    const int lane = tid & 31;
    const int wid  = tid >> 5;          // 0..3
    const int wr   = wid & 1;           // warp row (x64)
    const int wc   = wid >> 1;          // warp col (x64)

    // contiguous column-major tile range for this CTA
    int t0 = (int)((long long)blockIdx.x * nTiles / gridDim.x);
    int t1 = (int)(((long long)blockIdx.x + 1) * nTiles / gridDim.x);
    if (t0 >= t1) return;

    // ---- loader coords + precomputed swizzled smem offsets ----
    const int lc = tid & 7;             // 16B col within 64-wide chunk
    const int lr = tid >> 3;            // 0..15
    unsigned dstOff[8];
    #pragma unroll
    for (int p = 0; p < 8; p++)
        dstOff[p] = swz((unsigned)((p * 16 + lr) * 128 + lc * 16));

    // ---- ldsm address constants (swizzle strength reduction) ----
    const unsigned xa = (unsigned)(lane & 7) << 4;   // row-only XOR mask
    const unsigned qA = xa & 0x60;
    const unsigned pA = ((unsigned)(lane >> 4) << 4) ^ (xa & 0x10);
    const unsigned pB = ((unsigned)((lane >> 3) & 1) << 4) ^ (xa & 0x10);
    unsigned cbA[4], cbB[4];
    #pragma unroll
    for (int mt = 0; mt < 4; mt++)
        cbA[mt] = (unsigned)((wr * 64 + mt * 16 + (lane & 15)) * 128) + pA;
    #pragma unroll
    for (int np = 0; np < 4; np++)
        cbB[np] = (unsigned)((wc * 64 + np * 16 + (lane & 7) + ((lane >> 4) * 8)) * 128) + pB;

    const int g  = lane >> 2;           // epilogue row group
    const int cq = (lane & 3) * 2;      // epilogue col pair
    const int rtMask = (1 << tpsShift) - 1;

    int t = t0;
    while (t < t1) {
        const int strip = t >> tpsShift;
        int segEnd = (strip + 1) << tpsShift;
        if (segEnd > t1) segEnd = t1;
        const int colBase = strip * 128;
        const int steps = (segEnd - t) * 2;

        // B reload hazard: ensure all warps finished reading the previous
        // strip's B before overwriting it.
        __syncthreads();

        // ---- B strip load: 128 rows x K128 = 32KB, two 16KB K-halves ----
        #pragma unroll
        for (int ch = 0; ch < 2; ch++)
            #pragma unroll
            for (int p = 0; p < 8; p++)
                cp_async16(bBase + (unsigned)(ch * 16384) + dstOff[p],
                           g_Bbf + (size_t)(colBase + p * 16 + lr) * DMAX + ch * 64 + lc * 8);

        auto prefA = [&](int s) {       // A chunk prefetch; buffer = s & 3
            const int tt = t + (s >> 1);
            const int ch = s & 1;
            const int rowBase = (tt & rtMask) << 7;
            const unsigned aDst = sbase + (unsigned)((s & 3) * 16384);
            #pragma unroll
            for (int p = 0; p < 8; p++)
                cp_async16(aDst + dstOff[p],
                           g_Abf + (size_t)(rowBase + p * 16 + lr) * DMAX + ch * 64 + lc * 8);
            asm volatile("cp.async.commit_group;");
        };

        prefA(0);                       // group0 = B + A chunk 0
        if (steps > 1) prefA(1);
        if (steps > 2) prefA(2);

        float acc[4][8][4];

        for (int s = 0; s < steps; s++) {
            const int ch = s & 1;
            if (ch == 0) {
                #pragma unroll
                for (int i = 0; i < 4; i++)
                    #pragma unroll
                    for (int j = 0; j < 8; j++)
                        #pragma unroll
                        for (int k = 0; k < 4; k++)
                            acc[i][j][k] = 0.0f;
            }

            const int remain = steps - 1 - s;   // groups still outstanding after this
            if (remain >= 2)
                asm volatile("cp.async.wait_group 2;" ::: "memory");
            else if (remain == 1)
                asm volatile("cp.async.wait_group 1;" ::: "memory");
            else
                asm volatile("cp.async.wait_group 0;" ::: "memory");
            __syncthreads();            // sole barrier per step

            const unsigned aCur = sbase + (unsigned)((s & 3) * 16384);
            const unsigned bCur = bBase + (unsigned)(ch * 16384);

            #pragma unroll
            for (int kk = 0; kk < 4; kk++) {
                const unsigned colk = ((unsigned)(kk * 32)) ^ qA;  // 1 LOP3, shared
                unsigned afrag[4][4], bfrag[4][4];
                #pragma unroll
                for (int mt = 0; mt < 4; mt++)
                    ldsm_x4(afrag[mt], aCur + cbA[mt] + colk);
                #pragma unroll
                for (int np = 0; np < 4; np++)
                    ldsm_x4(bfrag[np], bCur + cbB[np] + colk);
                #pragma unroll
                for (int mt = 0; mt < 4; mt++)
                    #pragma unroll
                    for (int np = 0; np < 4; np++) {
                        mma16816(acc[mt][np * 2 + 0], afrag[mt], bfrag[np][0], bfrag[np][1]);
                        mma16816(acc[mt][np * 2 + 1], afrag[mt], bfrag[np][2], bfrag[np][3]);
                    }
            }
            // no post-compute barrier: prefA(s+3) writes buffer (s+3)&3 != s&3,
            // and buffer s&3 is next written by prefA(s+4), which can only be
            // issued after ALL warps pass the step s+1 entry barrier.

            if (s + 3 < steps) prefA(s + 3);

            if (ch == 1) {
                // ---- epilogue: -sqrt(max(a2 + b2 - 2ab, 0)) ----
                const int tt = t + (s >> 1);
                const int rowBase = (tt & rtMask) << 7;
                const float2* b2v =
                    reinterpret_cast<const float2*>(g_b2 + colBase + wc * 64);
                #pragma unroll
                for (int mt = 0; mt < 4; mt++) {
                    const int lr0 = wr * 64 + mt * 16 + g;
                    const float a20 = __ldg(g_a2 + rowBase + lr0);
                    const float a21 = __ldg(g_a2 + rowBase + lr0 + 8);
                    const long long grow0 = rowBase + lr0;
                    #pragma unroll
                    for (int nt = 0; nt < 8; nt++) {
                        const float2 b2 = __ldg(b2v + nt * 4 + (lane & 3));
                        const int gcol = colBase + wc * 64 + nt * 8 + cq;

                        float d00 = fmaf(-2.0f, acc[mt][nt][0], a20 + b2.x);
                        float d01 = fmaf(-2.0f, acc[mt][nt][1], a20 + b2.y);
                        float d10 = fmaf(-2.0f, acc[mt][nt][2], a21 + b2.x);
                        float d11 = fmaf(-2.0f, acc[mt][nt][3], a21 + b2.y);

                        st_cs_v2(out + grow0 * M + gcol, neg_sqrt(d00), neg_sqrt(d01));
                        st_cs_v2(out + (grow0 + 8) * M + gcol, neg_sqrt(d10), neg_sqrt(d11));
                    }
                }
            }
        }
        t = segEnd;
    }
}

// ---------------------------------------------------------------------------
extern "C" void kernel_launch(void* const* d_in, const int* in_sizes, int n_in,
                              void* d_out, int out_size) {
    const float* zA = (const float*)d_in[0];   // z_anc     [N, 128]
    const float* zB = (const float*)d_in[1];   // z_pos_neg [M, 128]
    const int N = in_sizes[0] / DMAX;
    const int M = in_sizes[1] / DMAX;

    const int totalWarps = N + M;
    prep_fused<<<(totalWarps * 32 + 255) / 256, 256>>>(zA, zB, N, M);

    int sms = 148;
    cudaDeviceGetAttribute(&sms, cudaDevAttrMultiProcessorCount, 0);

    cudaFuncSetAttribute(dist_gemm_kernel,
                         cudaFuncAttributeMaxDynamicSharedMemorySize, SMEM_BYTES);

    const int tps = N / 128;                   // row tiles per column strip
    int tpsShift = 0;
    while ((1 << tpsShift) < tps) tpsShift++;
    const int nTiles = (M / 128) * tps;        // column-major: strip * tps + rowTile

    int grid = 2 * sms;
    if (grid > nTiles) grid = nTiles;
    if (grid < 1) grid = 1;

    dist_gemm_kernel<<<grid, 128, SMEM_BYTES>>>((float*)d_out, M, nTiles, tpsShift);
}